// round 3
// baseline (speedup 1.0000x reference)
#include <cuda_runtime.h>

#define N_COL 256
#define N_ROW 256
#define N_CELLS (N_COL * N_ROW)
#define N_WORDS (N_CELLS / 32)          // 2048 bitmask words
#define N_AGENT_PTS (64 * 1001)         // 64064 (divisible by 4)
#define N_PTS4 (N_AGENT_PTS / 4)        // 16016 float4s per axis
#define BATCH 512
#define N_TOTAL (BATCH * N_CELLS)

#define SCAT_BLOCKS 64
#define SCAT_THREADS 1024
#define WORDS_PER_BLK (N_WORDS / SCAT_BLOCKS)   // 32
#define CELLS_PER_BLK (WORDS_PER_BLK * 32)      // 1024

// Scratch (allocation-free rule: __device__ globals).
// All of these are plain-overwritten every call (no init kernel), except
// g_arrive which self-resets via atomicInc wrap -> deterministic replays.
__device__ __align__(16) unsigned int g_bits[N_WORDS];
__device__ unsigned int g_counts[SCAT_BLOCKS];
__device__ unsigned int g_arrive;       // zero-init at load; wraps to 0 each call
__device__ unsigned int g_total;

// rotated cell index for one point, or -1 if not in box
__device__ __forceinline__ int point_cell(float x, float y) {
    float fx = x * (float)N_COL;
    float fy = y * (float)N_ROW;
    float cx = floorf(fx);
    float cy = floorf(fy);
    float rx = fx - cx;
    float ry = fy - cy;
    bool in_box = (rx >= 0.25f) && (rx <= 0.75f) && (ry >= 0.25f) && (ry <= 0.75f);
    if (!in_box) return -1;
    int ix = min(max((int)cx, 0), N_COL - 1);
    int iy = min(max((int)cy, 0), N_ROW - 1);
    // rot90 CCW folded in: source cell (ix,iy) -> output k = (255-iy)*256 + ix
    return (N_ROW - 1 - iy) * N_COL + ix;
}

// Gather-style scatter: each block owns 1024 cells, scans ALL points (L2-hit
// after first touch), accumulates into private smem bitmask, overwrites its
// global words with plain stores. No pre-zeroed global state required.
__global__ void __launch_bounds__(SCAT_THREADS)
k_scatter(const float4* __restrict__ ax4, const float4* __restrict__ ay4) {
    __shared__ unsigned int s_bits[WORDS_PER_BLK];
    int t = threadIdx.x;
    if (t < WORDS_PER_BLK) s_bits[t] = 0u;
    __syncthreads();

    const int kbase = blockIdx.x * CELLS_PER_BLK;

    #pragma unroll 4
    for (int j = t; j < N_PTS4; j += SCAT_THREADS) {
        float4 x = ax4[j];
        float4 y = ay4[j];
        int k;
        k = point_cell(x.x, y.x);
        if (k >= kbase && k < kbase + CELLS_PER_BLK) {
            int r = k - kbase; atomicOr(&s_bits[r >> 5], 1u << (r & 31));
        }
        k = point_cell(x.y, y.y);
        if (k >= kbase && k < kbase + CELLS_PER_BLK) {
            int r = k - kbase; atomicOr(&s_bits[r >> 5], 1u << (r & 31));
        }
        k = point_cell(x.z, y.z);
        if (k >= kbase && k < kbase + CELLS_PER_BLK) {
            int r = k - kbase; atomicOr(&s_bits[r >> 5], 1u << (r & 31));
        }
        k = point_cell(x.w, y.w);
        if (k >= kbase && k < kbase + CELLS_PER_BLK) {
            int r = k - kbase; atomicOr(&s_bits[r >> 5], 1u << (r & 31));
        }
    }
    __syncthreads();

    // Epilogue: warp 0 writes the 32 words + partial popcount; last-arriving
    // block finalizes the total. atomicInc wraps back to 0 -> replay-safe.
    if (t < 32) {
        unsigned int w = s_bits[t];
        g_bits[blockIdx.x * WORDS_PER_BLK + t] = w;
        unsigned int c = __popc(w);
        #pragma unroll
        for (int o = 16; o > 0; o >>= 1) c += __shfl_down_sync(0xffffffffu, c, o);
        if (t == 0) {
            g_counts[blockIdx.x] = c;
            __threadfence();
            unsigned int old = atomicInc(&g_arrive, SCAT_BLOCKS - 1);
            if (old == SCAT_BLOCKS - 1) {      // I am the last block
                unsigned int tot = 0;
                #pragma unroll
                for (int b = 0; b < SCAT_BLOCKS; b++) tot += g_counts[b];
                g_total = tot;
            }
        }
    }
}

// Apply: out = in * mask * scale. Bitmask (8 KB) is L2-resident.
__global__ void __launch_bounds__(256) k_apply(const float4* __restrict__ in,
                                               float4* __restrict__ out) {
    int i = blockIdx.x * blockDim.x + threadIdx.x;   // one float4 per thread
    unsigned int cnt = g_total;
    float scale = (float)N_CELLS / (float)(N_CELLS - cnt);

    int m = i & (N_CELLS / 4 - 1);           // float4 index within the 65536 row
    unsigned int word = g_bits[m >> 3];      // cell base k = m*4; word = k>>5
    unsigned int b = word >> ((m & 7) * 4);  // 4 adjacent bits for these cells

    float4 v = in[i];
    v.x = (b & 1u) ? 0.0f : v.x * scale;
    v.y = (b & 2u) ? 0.0f : v.y * scale;
    v.z = (b & 4u) ? 0.0f : v.z * scale;
    v.w = (b & 8u) ? 0.0f : v.w * scale;
    out[i] = v;
}

extern "C" void kernel_launch(void* const* d_in, const int* in_sizes, int n_in,
                              void* d_out, int out_size) {
    const float* input = (const float*)d_in[0];
    const float* agents_x = (const float*)d_in[1];
    const float* agents_y = (const float*)d_in[2];
    float* out = (float*)d_out;

    k_scatter<<<SCAT_BLOCKS, SCAT_THREADS>>>((const float4*)agents_x,
                                             (const float4*)agents_y);

    int n4 = N_TOTAL / 4;  // 8,388,608 float4s
    k_apply<<<n4 / 256, 256>>>((const float4*)input, (float4*)out);
}

// round 4
// speedup vs baseline: 1.2348x; 1.2348x over previous
#include <cuda_runtime.h>

#define N_COL 256
#define N_ROW 256
#define N_CELLS (N_COL * N_ROW)
#define N_WORDS (N_CELLS / 32)          // 2048 bitmask words
#define N_AGENT_PTS (64 * 1001)         // 64064
#define BATCH 512
#define N_M4 (N_CELLS / 4)              // 16384 float4s per batch row
#define BPT 4                           // batch rows per apply thread

// Scratch: [0..N_WORDS) bitmask, [N_WORDS] touched-cell counter.
// Zeroed each call by a cudaMemsetAsync graph node.
__device__ unsigned int g_state[N_WORDS + 1];

// scatter: mark rotated cell bit; count newly-set cells exactly
__global__ void k_scatter(const float* __restrict__ ax, const float* __restrict__ ay) {
    int i = blockIdx.x * blockDim.x + threadIdx.x;
    if (i >= N_AGENT_PTS) return;
    float fx = ax[i] * (float)N_COL;
    float fy = ay[i] * (float)N_ROW;
    float cx = floorf(fx);
    float cy = floorf(fy);
    float rx = fx - cx;
    float ry = fy - cy;
    bool in_box = (rx >= 0.25f) && (rx <= 0.75f) && (ry >= 0.25f) && (ry <= 0.75f);
    if (in_box) {
        int ix = min(max((int)cx, 0), N_COL - 1);
        int iy = min(max((int)cy, 0), N_ROW - 1);
        // rot90 CCW folded in: source cell (ix,iy) -> output k = (255-iy)*256 + ix
        int k = (N_ROW - 1 - iy) * N_COL + ix;
        unsigned int bit = 1u << (k & 31);
        unsigned int old = atomicOr(&g_state[k >> 5], bit);
        if (!(old & bit)) atomicAdd(&g_state[N_WORDS], 1u);
    }
}

// apply: out = in * mask * scale.
// Thread layout: m = mask position (float4 granularity), each thread handles
// BPT=4 consecutive batch rows at that m -> mask word + scale amortized over
// 4 independent 16B loads (MLP=4).
__global__ void __launch_bounds__(256) k_apply(const float4* __restrict__ in,
                                               float4* __restrict__ out) {
    int tid = blockIdx.x * blockDim.x + threadIdx.x;
    int m = tid & (N_M4 - 1);            // float4 index within a batch row
    int g = tid >> 14;                   // batch group (0..127)
    int b0 = g * BPT;

    unsigned int cnt = g_state[N_WORDS];
    float scale = (float)N_CELLS / (float)(N_CELLS - cnt);

    unsigned int word = g_state[m >> 3];
    unsigned int bits = (word >> ((m & 7) * 4)) & 0xFu;

    const float4* p = in + (long)b0 * N_M4 + m;
    float4* q = out + (long)b0 * N_M4 + m;

    // 4 independent loads issued before any use
    float4 v0 = p[0 * N_M4];
    float4 v1 = p[1 * N_M4];
    float4 v2 = p[2 * N_M4];
    float4 v3 = p[3 * N_M4];

    float sx = (bits & 1u) ? 0.0f : scale;
    float sy = (bits & 2u) ? 0.0f : scale;
    float sz = (bits & 4u) ? 0.0f : scale;
    float sw = (bits & 8u) ? 0.0f : scale;

    v0.x *= sx; v0.y *= sy; v0.z *= sz; v0.w *= sw;
    v1.x *= sx; v1.y *= sy; v1.z *= sz; v1.w *= sw;
    v2.x *= sx; v2.y *= sy; v2.z *= sz; v2.w *= sw;
    v3.x *= sx; v3.y *= sy; v3.z *= sz; v3.w *= sw;

    q[0 * N_M4] = v0;
    q[1 * N_M4] = v1;
    q[2 * N_M4] = v2;
    q[3 * N_M4] = v3;
}

extern "C" void kernel_launch(void* const* d_in, const int* in_sizes, int n_in,
                              void* d_out, int out_size) {
    const float* input = (const float*)d_in[0];
    const float* agents_x = (const float*)d_in[1];
    const float* agents_y = (const float*)d_in[2];
    float* out = (float*)d_out;

    void* state_ptr = nullptr;
    cudaGetSymbolAddress(&state_ptr, g_state);
    cudaMemsetAsync(state_ptr, 0, sizeof(unsigned int) * (N_WORDS + 1));

    k_scatter<<<(N_AGENT_PTS + 255) / 256, 256>>>(agents_x, agents_y);

    // threads = 16384 m-positions * 128 batch groups = 2,097,152 -> 8192 blocks
    int total_threads = N_M4 * (BATCH / BPT);
    k_apply<<<total_threads / 256, 256>>>((const float4*)input, (float4*)out);
}

// round 5
// speedup vs baseline: 1.2403x; 1.0045x over previous
#include <cuda_runtime.h>

#define N_COL 256
#define N_ROW 256
#define N_CELLS (N_COL * N_ROW)
#define N_WORDS (N_CELLS / 32)          // 2048 bitmask words
#define N_AGENT_PTS (64 * 1001)         // 64064
#define BATCH 512
#define N_M4 (N_CELLS / 4)              // 16384 float4s per batch row
#define BPT 4                           // batch rows per apply thread

#define SCAT_BLOCKS 64
#define SCAT_THREADS 1024

// Scratch: [0..N_WORDS) bitmask, [N_WORDS] touched-cell counter.
__device__ unsigned int g_state[N_WORDS + 1];
// Monotonic grid-barrier arrival counter. Never reset -> no stale-window
// race; behavior is identical on every call (each call adds exactly
// SCAT_BLOCKS). Wraparound-safe compare below.
__device__ unsigned int g_bar;

// Fused zero + scatter in ONE launch (saves a memset graph node).
__global__ void __launch_bounds__(SCAT_THREADS)
k_scatter(const float* __restrict__ ax, const float* __restrict__ ay) {
    int tid = threadIdx.x;
    int i = blockIdx.x * SCAT_THREADS + tid;

    // Phase 1: zero the 2049 state words (done by the first 3 blocks' threads)
    if (i < N_WORDS + 1) g_state[i] = 0u;
    __threadfence();
    __syncthreads();

    // Grid barrier: one spinner per block on a monotonic counter.
    if (tid == 0) {
        unsigned int v = atomicAdd(&g_bar, 1u) + 1u;             // my arrival #
        unsigned int target = ((v - 1u) / SCAT_BLOCKS + 1u) * SCAT_BLOCKS;
        for (;;) {
            unsigned int cur;
            asm volatile("ld.acquire.gpu.u32 %0, [%1];" : "=r"(cur) : "l"(&g_bar));
            if ((int)(cur - target) >= 0) break;                 // wrap-safe
        }
    }
    __syncthreads();

    // Phase 2: scatter — mark rotated cell bit; count newly-set cells exactly
    if (i < N_AGENT_PTS) {
        float fx = ax[i] * (float)N_COL;
        float fy = ay[i] * (float)N_ROW;
        float cx = floorf(fx);
        float cy = floorf(fy);
        float rx = fx - cx;
        float ry = fy - cy;
        bool in_box = (rx >= 0.25f) && (rx <= 0.75f) && (ry >= 0.25f) && (ry <= 0.75f);
        if (in_box) {
            int ix = min(max((int)cx, 0), N_COL - 1);
            int iy = min(max((int)cy, 0), N_ROW - 1);
            // rot90 CCW folded in: (ix,iy) -> k = (255-iy)*256 + ix
            int k = (N_ROW - 1 - iy) * N_COL + ix;
            unsigned int bit = 1u << (k & 31);
            unsigned int old = atomicOr(&g_state[k >> 5], bit);
            if (!(old & bit)) atomicAdd(&g_state[N_WORDS], 1u);
        }
    }
}

// apply: out = in * mask * scale.  m = mask position (float4 granularity),
// each thread handles BPT=4 batch rows at that m -> mask + scale amortized,
// 4 independent 16B streaming loads (MLP=4).
__global__ void __launch_bounds__(256) k_apply(const float4* __restrict__ in,
                                               float4* __restrict__ out) {
    int tid = blockIdx.x * blockDim.x + threadIdx.x;
    int m = tid & (N_M4 - 1);            // float4 index within a batch row
    int g = tid >> 14;                   // batch group (0..127)
    int b0 = g * BPT;

    unsigned int cnt = g_state[N_WORDS];
    float scale = (float)N_CELLS / (float)(N_CELLS - cnt);

    unsigned int word = g_state[m >> 3];
    unsigned int bits = (word >> ((m & 7) * 4)) & 0xFu;

    const float4* p = in + (long)b0 * N_M4 + m;
    float4* q = out + (long)b0 * N_M4 + m;

    // 4 independent read-once loads, evict-first so L2 stays free for writes
    float4 v0 = __ldcs(p + 0 * N_M4);
    float4 v1 = __ldcs(p + 1 * N_M4);
    float4 v2 = __ldcs(p + 2 * N_M4);
    float4 v3 = __ldcs(p + 3 * N_M4);

    float sx = (bits & 1u) ? 0.0f : scale;
    float sy = (bits & 2u) ? 0.0f : scale;
    float sz = (bits & 4u) ? 0.0f : scale;
    float sw = (bits & 8u) ? 0.0f : scale;

    v0.x *= sx; v0.y *= sy; v0.z *= sz; v0.w *= sw;
    v1.x *= sx; v1.y *= sy; v1.z *= sz; v1.w *= sw;
    v2.x *= sx; v2.y *= sy; v2.z *= sz; v2.w *= sw;
    v3.x *= sx; v3.y *= sy; v3.z *= sz; v3.w *= sw;

    q[0 * N_M4] = v0;
    q[1 * N_M4] = v1;
    q[2 * N_M4] = v2;
    q[3 * N_M4] = v3;
}

extern "C" void kernel_launch(void* const* d_in, const int* in_sizes, int n_in,
                              void* d_out, int out_size) {
    const float* input = (const float*)d_in[0];
    const float* agents_x = (const float*)d_in[1];
    const float* agents_y = (const float*)d_in[2];
    float* out = (float*)d_out;

    k_scatter<<<SCAT_BLOCKS, SCAT_THREADS>>>(agents_x, agents_y);

    int total_threads = N_M4 * (BATCH / BPT);   // 2,097,152 -> 8192 blocks
    k_apply<<<total_threads / 256, 256>>>((const float4*)input, (float4*)out);
}

// round 6
// speedup vs baseline: 1.2565x; 1.0131x over previous
#include <cuda_runtime.h>
#include <cuda_device_runtime_api.h>

#define N_COL 256
#define N_ROW 256
#define N_CELLS (N_COL * N_ROW)
#define N_WORDS (N_CELLS / 32)          // 2048 bitmask words
#define N_AGENT_PTS (64 * 1001)         // 64064
#define BATCH 512
#define N_M4 (N_CELLS / 4)              // 16384 float4s per batch row
#define BPT 4                           // batch rows per apply thread

#define SCAT_BLOCKS 64
#define SCAT_THREADS 1024

// Scratch: [0..N_WORDS) bitmask, [N_WORDS] touched-cell counter.
__device__ unsigned int g_state[N_WORDS + 1];
// Monotonic grid-barrier arrival counter (never reset -> replay-safe).
__device__ unsigned int g_bar;

// Fused zero + scatter, single launch. Triggers PDL at entry so k_apply's
// blocks begin launching while this runs.
__global__ void __launch_bounds__(SCAT_THREADS)
k_scatter(const float* __restrict__ ax, const float* __restrict__ ay) {
    cudaTriggerProgrammaticLaunchCompletion();

    int tid = threadIdx.x;
    int i = blockIdx.x * SCAT_THREADS + tid;

    // Phase 1: zero the 2049 state words
    if (i < N_WORDS + 1) g_state[i] = 0u;
    __threadfence();
    __syncthreads();

    // Grid barrier: one spinner per block on a monotonic counter.
    if (tid == 0) {
        unsigned int v = atomicAdd(&g_bar, 1u) + 1u;             // my arrival #
        unsigned int target = ((v - 1u) / SCAT_BLOCKS + 1u) * SCAT_BLOCKS;
        for (;;) {
            unsigned int cur;
            asm volatile("ld.acquire.gpu.u32 %0, [%1];" : "=r"(cur) : "l"(&g_bar));
            if ((int)(cur - target) >= 0) break;                 // wrap-safe
        }
    }
    __syncthreads();

    // Phase 2: scatter — mark rotated cell bit; count newly-set cells exactly
    if (i < N_AGENT_PTS) {
        float fx = ax[i] * (float)N_COL;
        float fy = ay[i] * (float)N_ROW;
        float cx = floorf(fx);
        float cy = floorf(fy);
        float rx = fx - cx;
        float ry = fy - cy;
        bool in_box = (rx >= 0.25f) && (rx <= 0.75f) && (ry >= 0.25f) && (ry <= 0.75f);
        if (in_box) {
            int ix = min(max((int)cx, 0), N_COL - 1);
            int iy = min(max((int)cy, 0), N_ROW - 1);
            // rot90 CCW folded in: (ix,iy) -> k = (255-iy)*256 + ix
            int k = (N_ROW - 1 - iy) * N_COL + ix;
            unsigned int bit = 1u << (k & 31);
            unsigned int old = atomicOr(&g_state[k >> 5], bit);
            if (!(old & bit)) atomicAdd(&g_state[N_WORDS], 1u);
        }
    }
}

// apply: out = in * mask * scale. Input loads are issued BEFORE the grid
// dependency sync (they don't depend on the mask), so the scatter kernel
// hides entirely under this kernel's own DRAM traffic.
__global__ void __launch_bounds__(256) k_apply(const float4* __restrict__ in,
                                               float4* __restrict__ out) {
    int tid = blockIdx.x * blockDim.x + threadIdx.x;
    int m = tid & (N_M4 - 1);            // float4 index within a batch row
    int g = tid >> 14;                   // batch group (0..127)
    int b0 = g * BPT;

    const float4* p = in + (long)b0 * N_M4 + m;
    float4* q = out + (long)b0 * N_M4 + m;

    // 4 independent read-once loads — issued before waiting on scatter
    float4 v0 = __ldcs(p + 0 * N_M4);
    float4 v1 = __ldcs(p + 1 * N_M4);
    float4 v2 = __ldcs(p + 2 * N_M4);
    float4 v3 = __ldcs(p + 3 * N_M4);

    // Wait for scatter's writes to be visible, then read mask state
    cudaGridDependencySynchronize();

    unsigned int cnt = g_state[N_WORDS];
    float scale = (float)N_CELLS / (float)(N_CELLS - cnt);
    unsigned int word = g_state[m >> 3];
    unsigned int bits = (word >> ((m & 7) * 4)) & 0xFu;

    float sx = (bits & 1u) ? 0.0f : scale;
    float sy = (bits & 2u) ? 0.0f : scale;
    float sz = (bits & 4u) ? 0.0f : scale;
    float sw = (bits & 8u) ? 0.0f : scale;

    v0.x *= sx; v0.y *= sy; v0.z *= sz; v0.w *= sw;
    v1.x *= sx; v1.y *= sy; v1.z *= sz; v1.w *= sw;
    v2.x *= sx; v2.y *= sy; v2.z *= sz; v2.w *= sw;
    v3.x *= sx; v3.y *= sy; v3.z *= sz; v3.w *= sw;

    q[0 * N_M4] = v0;
    q[1 * N_M4] = v1;
    q[2 * N_M4] = v2;
    q[3 * N_M4] = v3;
}

extern "C" void kernel_launch(void* const* d_in, const int* in_sizes, int n_in,
                              void* d_out, int out_size) {
    const float* input = (const float*)d_in[0];
    const float* agents_x = (const float*)d_in[1];
    const float* agents_y = (const float*)d_in[2];
    float* out = (float*)d_out;

    // Primary: fused zero+scatter
    k_scatter<<<SCAT_BLOCKS, SCAT_THREADS>>>(agents_x, agents_y);

    // Secondary: apply, launched with programmatic dependent launch so its
    // blocks start (and begin streaming input) while scatter still runs.
    int total_threads = N_M4 * (BATCH / BPT);   // 2,097,152 -> 8192 blocks
    cudaLaunchConfig_t cfg = {};
    cfg.gridDim = dim3(total_threads / 256);
    cfg.blockDim = dim3(256);
    cfg.dynamicSmemBytes = 0;
    cfg.stream = 0;
    cudaLaunchAttribute attrs[1];
    attrs[0].id = cudaLaunchAttributeProgrammaticStreamSerialization;
    attrs[0].val.programmaticStreamSerializationAllowed = 1;
    cfg.attrs = attrs;
    cfg.numAttrs = 1;
    cudaLaunchKernelEx(&cfg, k_apply, (const float4*)input, (float4*)out);
}